// round 1
// baseline (speedup 1.0000x reference)
#include <cuda_runtime.h>

// Problem constants (fixed by the reference: B=2, G=64)
#define G3 (64 * 64 * 64)          // 262144 voxels per batch, power of two

// For each voxel v and batch b:
//   A[m][i] = alpha[b][m][i][v]          (3x3)
//   C[b][i][j][k][l][v] = sum_{mnop} A[m][i] A[n][j] A[o][k] A[p][l] C0[m][n][o][p]
// Staged per output-index i to keep register pressure at ~27+27+9.
__global__ void __launch_bounds__(256)
alphaC0_kernel(const float* __restrict__ alpha,
               const float* __restrict__ C0,
               float* __restrict__ out,
               int total)
{
    __shared__ float c0s[81];
    if (threadIdx.x < 81) c0s[threadIdx.x] = C0[threadIdx.x];
    __syncthreads();

    const int tid = blockIdx.x * blockDim.x + threadIdx.x;
    if (tid >= total) return;

    const int b = tid >> 18;            // / G3
    const int v = tid & (G3 - 1);       // % G3

    // Load the 3x3 alpha matrix for this voxel: A[m][i]
    float A[3][3];
#pragma unroll
    for (int m = 0; m < 3; m++)
#pragma unroll
        for (int i = 0; i < 3; i++)
            A[m][i] = __ldg(&alpha[((b * 3 + m) * 3 + i) * G3 + v]);

#pragma unroll
    for (int i = 0; i < 3; i++) {
        // Stage 1: T1[n][o][p] = sum_m A[m][i] * C0[m][n][o][p]
        float T1[27];
#pragma unroll
        for (int n = 0; n < 3; n++)
#pragma unroll
            for (int o = 0; o < 3; o++)
#pragma unroll
                for (int p = 0; p < 3; p++) {
                    float s = 0.0f;
#pragma unroll
                    for (int m = 0; m < 3; m++)
                        s = fmaf(A[m][i], c0s[((m * 3 + n) * 3 + o) * 3 + p], s);
                    T1[(n * 3 + o) * 3 + p] = s;
                }

        // Stage 2: T2[j][o][p] = sum_n A[n][j] * T1[n][o][p]
        float T2[27];
#pragma unroll
        for (int j = 0; j < 3; j++)
#pragma unroll
            for (int o = 0; o < 3; o++)
#pragma unroll
                for (int p = 0; p < 3; p++) {
                    float s = 0.0f;
#pragma unroll
                    for (int n = 0; n < 3; n++)
                        s = fmaf(A[n][j], T1[(n * 3 + o) * 3 + p], s);
                    T2[(j * 3 + o) * 3 + p] = s;
                }

        // Stage 3: T3[j][k][p] = sum_o A[o][k] * T2[j][o][p]   (reuses T1's regs)
        float T3[27];
#pragma unroll
        for (int j = 0; j < 3; j++)
#pragma unroll
            for (int k = 0; k < 3; k++)
#pragma unroll
                for (int p = 0; p < 3; p++) {
                    float s = 0.0f;
#pragma unroll
                    for (int o = 0; o < 3; o++)
                        s = fmaf(A[o][k], T2[(j * 3 + o) * 3 + p], s);
                    T3[(j * 3 + k) * 3 + p] = s;
                }

        // Stage 4 + store: C[b][i][j][k][l][v] = sum_p A[p][l] * T3[j][k][p]
        float* outb = out + (size_t)(b * 81 + i * 27) * G3 + v;
#pragma unroll
        for (int j = 0; j < 3; j++)
#pragma unroll
            for (int k = 0; k < 3; k++)
#pragma unroll
                for (int l = 0; l < 3; l++) {
                    float s = 0.0f;
#pragma unroll
                    for (int p = 0; p < 3; p++)
                        s = fmaf(A[p][l], T3[(j * 3 + k) * 3 + p], s);
                    outb[(size_t)((j * 3 + k) * 3 + l) * G3] = s;
                }
    }
}

extern "C" void kernel_launch(void* const* d_in, const int* in_sizes, int n_in,
                              void* d_out, int out_size)
{
    const float* alpha = (const float*)d_in[0];   // (B,3,3,G,G,G) float32
    const float* C0    = (const float*)d_in[1];   // (3,3,3,3) float32
    float* out         = (float*)d_out;           // (B,3,3,3,3,G,G,G) float32

    const int total = in_sizes[0] / 9;            // B * G^3 voxels
    const int threads = 256;
    const int blocks = (total + threads - 1) / threads;
    alphaC0_kernel<<<blocks, threads>>>(alpha, C0, out, total);
}

// round 2
// speedup vs baseline: 1.2080x; 1.2080x over previous
#include <cuda_runtime.h>

#define G3 (64 * 64 * 64)          // 262144 voxels per batch, power of two

// Per voxel: A[m][i] = alpha[b][m][i][v];  C_ijkl = sum_{mnop} A_mi A_nj A_ok A_pl C0_mnop
// Loop over i is ROLLED so registers recycle; stages fused pairwise so only
// T2[27] is ever fully live. Target <=64 regs -> 4 CTAs/SM.
__global__ void __launch_bounds__(256, 4)
alphaC0_kernel(const float* __restrict__ alpha,
               const float* __restrict__ C0,
               float* __restrict__ out,
               int total)
{
    __shared__ float c0s[81];
    if (threadIdx.x < 81) c0s[threadIdx.x] = C0[threadIdx.x];
    __syncthreads();

    const int tid = blockIdx.x * blockDim.x + threadIdx.x;
    if (tid >= total) return;

    const int b = tid >> 18;            // / G3
    const int v = tid & (G3 - 1);       // % G3

    // A[m][i]
    float A[3][3];
#pragma unroll
    for (int m = 0; m < 3; m++)
#pragma unroll
        for (int i = 0; i < 3; i++)
            A[m][i] = __ldg(&alpha[((b * 3 + m) * 3 + i) * G3 + v]);

    float* const outb0 = out + (size_t)b * 81 * G3 + v;

#pragma unroll 1
    for (int i = 0; i < 3; i++) {
        // a_m = A[m][i] without dynamic register indexing
        float a0, a1, a2;
        if (i == 0)      { a0 = A[0][0]; a1 = A[1][0]; a2 = A[2][0]; }
        else if (i == 1) { a0 = A[0][1]; a1 = A[1][1]; a2 = A[2][1]; }
        else             { a0 = A[0][2]; a1 = A[1][2]; a2 = A[2][2]; }

        // Fused stage1+2: T2[j][o][p] = sum_n A[n][j] * (sum_m a_m C0[m][n][o][p])
        float T2[27];
#pragma unroll
        for (int o = 0; o < 3; o++) {
#pragma unroll
            for (int p = 0; p < 3; p++) {
                float t1[3];
#pragma unroll
                for (int n = 0; n < 3; n++) {
                    t1[n] = fmaf(a0, c0s[((0 * 3 + n) * 3 + o) * 3 + p],
                            fmaf(a1, c0s[((1 * 3 + n) * 3 + o) * 3 + p],
                                 a2 * c0s[((2 * 3 + n) * 3 + o) * 3 + p]));
                }
#pragma unroll
                for (int j = 0; j < 3; j++) {
                    T2[(j * 3 + o) * 3 + p] =
                        fmaf(A[0][j], t1[0],
                        fmaf(A[1][j], t1[1],
                             A[2][j] * t1[2]));
                }
            }
        }

        // Fused stage3+4: per (j,k) build t3[p] then emit 3 outputs immediately
        float* const outb = outb0 + (size_t)(i * 27) * G3;
#pragma unroll
        for (int j = 0; j < 3; j++) {
#pragma unroll
            for (int k = 0; k < 3; k++) {
                float t3[3];
#pragma unroll
                for (int p = 0; p < 3; p++) {
                    t3[p] = fmaf(A[0][k], T2[(j * 3 + 0) * 3 + p],
                            fmaf(A[1][k], T2[(j * 3 + 1) * 3 + p],
                                 A[2][k] * T2[(j * 3 + 2) * 3 + p]));
                }
#pragma unroll
                for (int l = 0; l < 3; l++) {
                    outb[(size_t)((j * 3 + k) * 3 + l) * G3] =
                        fmaf(A[0][l], t3[0],
                        fmaf(A[1][l], t3[1],
                             A[2][l] * t3[2]));
                }
            }
        }
    }
}

extern "C" void kernel_launch(void* const* d_in, const int* in_sizes, int n_in,
                              void* d_out, int out_size)
{
    const float* alpha = (const float*)d_in[0];   // (B,3,3,G,G,G) float32
    const float* C0    = (const float*)d_in[1];   // (3,3,3,3) float32
    float* out         = (float*)d_out;           // (B,3,3,3,3,G,G,G) float32

    const int total = in_sizes[0] / 9;            // B * G^3 voxels
    const int threads = 256;
    const int blocks = (total + threads - 1) / threads;
    alphaC0_kernel<<<blocks, threads>>>(alpha, C0, out, total);
}

// round 3
// speedup vs baseline: 1.3275x; 1.0989x over previous
#include <cuda_runtime.h>

#define G3 (64 * 64 * 64)          // 262144 voxels per batch
#define PAIRS_PER_B (G3 / 2)       // 131072 voxel pairs per batch

typedef unsigned long long u64;

// Packed f32x2 ops — ptxas never auto-fuses these; must be inline PTX.
__device__ __forceinline__ u64 f2fma(u64 a, u64 b, u64 c) {
    u64 d; asm("fma.rn.f32x2 %0, %1, %2, %3;" : "=l"(d) : "l"(a), "l"(b), "l"(c)); return d;
}
__device__ __forceinline__ u64 f2mul(u64 a, u64 b) {
    u64 d; asm("mul.rn.f32x2 %0, %1, %2;" : "=l"(d) : "l"(a), "l"(b)); return d;
}
__device__ __forceinline__ u64 f2dup(float x) {
    u64 d; asm("mov.b64 %0, {%1, %1};" : "=l"(d) : "f"(x)); return d;
}

// One thread = one voxel PAIR (v, v+1). All tensors have voxel innermost, so
// every load/store is a natural 8-byte vector and all math is fma.rn.f32x2.
__global__ void __launch_bounds__(256, 2)
alphaC0_kernel(const float* __restrict__ alpha,
               const float* __restrict__ C0,
               float* __restrict__ out,
               int total_pairs)
{
    __shared__ u64 c0s2[81];       // C0 value duplicated into both f32x2 lanes
    if (threadIdx.x < 81) c0s2[threadIdx.x] = f2dup(C0[threadIdx.x]);
    __syncthreads();

    const int tid = blockIdx.x * blockDim.x + threadIdx.x;
    if (tid >= total_pairs) return;

    const int b = tid >> 17;                   // / PAIRS_PER_B
    const int v = (tid & (PAIRS_PER_B - 1)) * 2;

    // A2[m][i] = packed { A(v)[m][i], A(v+1)[m][i] }
    u64 A2[3][3];
#pragma unroll
    for (int m = 0; m < 3; m++)
#pragma unroll
        for (int i = 0; i < 3; i++)
            A2[m][i] = *reinterpret_cast<const u64*>(
                &alpha[(size_t)((b * 3 + m) * 3 + i) * G3 + v]);

    const char* outb0 = reinterpret_cast<const char*>(out)
                      + ((size_t)b * 81 * G3 + v) * sizeof(float);

#pragma unroll 1
    for (int i = 0; i < 3; i++) {
        u64 a0, a1, a2;
        if (i == 0)      { a0 = A2[0][0]; a1 = A2[1][0]; a2 = A2[2][0]; }
        else if (i == 1) { a0 = A2[0][1]; a1 = A2[1][1]; a2 = A2[2][1]; }
        else             { a0 = A2[0][2]; a1 = A2[1][2]; a2 = A2[2][2]; }

        // Fused stage1+2: T2[j][o][p] = sum_n A[n][j] * (sum_m a_m C0[m][n][o][p])
        u64 T2[27];
#pragma unroll
        for (int o = 0; o < 3; o++) {
#pragma unroll
            for (int p = 0; p < 3; p++) {
                u64 t1[3];
#pragma unroll
                for (int n = 0; n < 3; n++) {
                    t1[n] = f2fma(a0, c0s2[((0 * 3 + n) * 3 + o) * 3 + p],
                            f2fma(a1, c0s2[((1 * 3 + n) * 3 + o) * 3 + p],
                            f2mul(a2, c0s2[((2 * 3 + n) * 3 + o) * 3 + p])));
                }
#pragma unroll
                for (int j = 0; j < 3; j++) {
                    T2[(j * 3 + o) * 3 + p] =
                        f2fma(A2[0][j], t1[0],
                        f2fma(A2[1][j], t1[1],
                        f2mul(A2[2][j], t1[2])));
                }
            }
        }

        // Fused stage3+4: per (j,k) build t3[p], emit 3 packed stores immediately
        const char* outb = outb0 + (size_t)(i * 27) * G3 * sizeof(float);
#pragma unroll
        for (int j = 0; j < 3; j++) {
#pragma unroll
            for (int k = 0; k < 3; k++) {
                u64 t3[3];
#pragma unroll
                for (int p = 0; p < 3; p++) {
                    t3[p] = f2fma(A2[0][k], T2[(j * 3 + 0) * 3 + p],
                            f2fma(A2[1][k], T2[(j * 3 + 1) * 3 + p],
                            f2mul(A2[2][k], T2[(j * 3 + 2) * 3 + p])));
                }
#pragma unroll
                for (int l = 0; l < 3; l++) {
                    *reinterpret_cast<u64*>(const_cast<char*>(
                        outb + (size_t)((j * 3 + k) * 3 + l) * G3 * sizeof(float))) =
                        f2fma(A2[0][l], t3[0],
                        f2fma(A2[1][l], t3[1],
                        f2mul(A2[2][l], t3[2])));
                }
            }
        }
    }
}

extern "C" void kernel_launch(void* const* d_in, const int* in_sizes, int n_in,
                              void* d_out, int out_size)
{
    const float* alpha = (const float*)d_in[0];   // (B,3,3,G,G,G) float32
    const float* C0    = (const float*)d_in[1];   // (3,3,3,3) float32
    float* out         = (float*)d_out;           // (B,3,3,3,3,G,G,G) float32

    const int total_pairs = in_sizes[0] / 18;     // B * G^3 / 2
    const int threads = 256;
    const int blocks = (total_pairs + threads - 1) / threads;
    alphaC0_kernel<<<blocks, threads>>>(alpha, C0, out, total_pairs);
}